// round 12
// baseline (speedup 1.0000x reference)
#include <cuda_runtime.h>

// Problem constants
#define K_CODES 1024
#define D_DIM   64
#define B_SZ    16
#define T_LEN   8192
#define N_VEC   (B_SZ * T_LEN)     // 131072 vectors
#define TPB     256
#define VV      128                // vectors per pair-tile
#define CH      64                 // codes per smem chunk
#define KSPLIT  512                // codes per CTA (half the codebook)
#define NPAIR   (N_VEC / VV)       // 1024 vector groups
#define NCTA    (2 * NPAIR)        // 2048 assign CTAs

typedef unsigned long long u64;

// Packed fp32x2 ops (sm_103a; PTX-only, ptxas never auto-fuses)
#define FMA_X2(d, a, b, c) \
    asm("fma.rn.f32x2 %0, %1, %2, %3;" : "=l"(d) : "l"(a), "l"(b), "l"(c))
#define PACK_X2(d, lo, hi) \
    asm("mov.b64 %0, {%1, %2};" : "=l"(d) : "f"(lo), "f"(hi))
#define UNPACK_X2(lo, hi, s) \
    asm("mov.b64 {%0, %1}, %2;" : "=f"(lo), "=f"(hi) : "l"(s))
#define LDS_V2U64(p0, p1, addr) \
    asm("ld.shared.v2.u64 {%0, %1}, [%2];" : "=l"(p0), "=l"(p1) : "r"(addr))
#define LDS_V2F32(f0, f1, addr) \
    asm("ld.shared.v2.f32 {%0, %1}, [%2];" : "=f"(f0), "=f"(f1) : "r"(addr))
#define STS_V4F32(addr, f0, f1, f2, f3) \
    asm volatile("st.shared.v4.f32 [%0], {%1,%2,%3,%4};" \
        :: "r"(addr), "f"(f0), "f"(f1), "f"(f2), "f"(f3))
#define LDS_F32(f, addr) \
    asm("ld.shared.f32 %0, [%1];" : "=f"(f) : "r"(addr))
#define STS_U32(addr, v) \
    asm volatile("st.shared.u32 [%0], %1;" :: "r"(addr), "r"(v) : "memory")
#define LDS_U32(v, addr) \
    asm("ld.shared.u32 %0, [%1];" : "=r"(v) : "r"(addr))
// Vector float reduction (sm_90+ baseline; no arch-'a' feature needed)
#define REDG_ADD_V4F32(ptr, a0, a1, a2, a3) \
    asm volatile("red.global.add.v4.f32 [%0], {%1,%2,%3,%4};" \
        :: "l"(ptr), "f"(a0), "f"(a1), "f"(a2), "f"(a3) : "memory")

// Scratch (allocation-free rule -> __device__ globals)
__device__ float    g_dw[K_CODES * D_DIM];
__device__ int      g_counts[K_CODES];
__device__ float    g_enorm[K_CODES];
__device__ u64      g_keys[N_VEC];      // per-vector packed (score|idx)
__device__ unsigned g_pair[NPAIR];      // per-pair tickets
__device__ unsigned g_done;             // global finalize ticket

// Dynamic smem layout (bytes) — exactly 48KB, zero static smem:
//   [0, 32768)       x tile: 64 d-rows x 512B (swizzled f32x2 vector-pairs)
//   [32768, 49152)   e tile: 64 code-rows x 256B (64 floats)
//   red2 (128 x u64 argmin cells) ALIASES the first 1KB of the e tile
//   (dead after the last chunk's compute; barrier-separated).
//   flag word at ES_OFF + 2048 (also dead e-tile space).
#define XS_OFF   0
#define ES_OFF   32768
#define FLAG_OFF (ES_OFF + 2048)
#define SMEM_BYTES 49152

// Init: reset all scratch + code norms (warp per code, shuffle reduce).
// 131072 threads.
__global__ void init_kernel(const float* __restrict__ emb) {
    const int gt = blockIdx.x * blockDim.x + threadIdx.x;

    g_keys[gt] = 0xFFFFFFFFFFFFFFFFull;
    if (gt < K_CODES * D_DIM) g_dw[gt] = 0.0f;
    if (gt < K_CODES) g_counts[gt] = 0;
    if (gt < NPAIR)   g_pair[gt] = 0u;
    if (gt == 0)      g_done = 0u;

    if (gt < K_CODES * 32) {           // 1024 warps: one per code
        const int lane = gt & 31;
        const int code = gt >> 5;
        const float* e = emb + code * D_DIM;
        float v0 = e[lane], v1 = e[lane + 32];
        float s = fmaf(v0, v0, v1 * v1);
        #pragma unroll
        for (int o = 16; o > 0; o >>= 1)
            s += __shfl_xor_sync(0xFFFFFFFFu, s, o);
        if (lane == 0) g_enorm[code] = s;
    }
}

// GEMM-tiled assignment, K-split across CTA pairs for wave balance.
// CTA blk: pair = blk>>1 owns 128 vectors; half = blk&1 scans codes
// [half*512, half*512+512) in 8 chunks of 64. Same micro-kernel as before:
// thread (tv=tid&15, tc=tid>>4) does 8 vectors x 4 codes via fma.rn.f32x2.
// Cross-CTA argmin merge via global u64 atomicMin; the SECOND pair CTA to
// finish (ticket) runs the epilogue from its own smem x tile; the LAST
// epilogue CTA (global ticket) computes new_embeddings.
__global__ void __launch_bounds__(TPB, 2) assign_kernel(
    const float* __restrict__ x,
    const float* __restrict__ emb,
    float* __restrict__ outq,
    float* __restrict__ out_emb)
{
    extern __shared__ char sm[];
    const unsigned sbase = (unsigned)__cvta_generic_to_shared(sm);
    const unsigned xs  = sbase + XS_OFF;
    const unsigned esb = sbase + ES_OFF;
    u64* red2 = (u64*)(sm + ES_OFF);   // aliases e tile (dead after main loop)

    const int tid   = threadIdx.x;
    const int tv    = tid & 15;
    const int tc    = tid >> 4;
    const int blk   = blockIdx.x;
    const int pair  = blk >> 1;
    const int half  = blk & 1;
    const int b     = pair >> 6;                 // 64 pairs per batch row
    const int t0    = (pair << 7) & (T_LEN - 1); // 128 vectors per pair
    const int cbase = half << 9;                 // 0 or 512

    // Load x tile: xs[d][swizzled pair columns].
    // Pair p lives at byte (((p&~1)<<3) ^ (((p>>4)&3)<<4)) + ((p&1)<<3).
    {
        const float* xb = x + ((size_t)(b << 6)) * T_LEN + t0;
        #pragma unroll
        for (int i4 = tid; i4 < (D_DIM * VV) / 4; i4 += TPB) {   // 2048 float4
            int d = i4 >> 5, v4 = i4 & 31;
            float4 val = *(const float4*)(xb + (size_t)d * T_LEN + v4 * 4);
            unsigned a = xs + d * 512 + (((unsigned)(v4 << 4)) ^ (((v4 >> 3) & 3) << 4));
            STS_V4F32(a, val.x, val.y, val.z, val.w);
        }
    }

    float best[8];
    int   bidx[8];
    #pragma unroll
    for (int k = 0; k < 8; k++) { best[k] = 3.402823466e38f; bidx[k] = 0; }

    // Per-thread swizzled x-line base: first 16B at xlane, second at xlane^16.
    const unsigned xlane = ((unsigned)(tv * 32)) ^ ((((unsigned)tv >> 2) & 3) << 4);

    // This thread's 4 float4 slots within each 1024-float4 e chunk.
    const float4* emb4 = (const float4*)emb;
    float4 pf[4];
    #pragma unroll
    for (int j = 0; j < 4; j++)
        pf[j] = emb4[((size_t)cbase << 4) + (size_t)(tid + j * TPB)];

    for (int c0 = cbase; c0 < cbase + KSPLIT; c0 += CH) {
        __syncthreads();   // prev chunk's compute (and x-tile stores) done
        #pragma unroll
        for (int j = 0; j < 4; j++) {
            int i4 = tid + j * TPB;
            STS_V4F32(esb + (i4 >> 4) * 256 + (i4 & 15) * 16,
                      pf[j].x, pf[j].y, pf[j].z, pf[j].w);
        }
        __syncthreads();

        // Prefetch next chunk; scoreboard wait lands at next STS (after
        // this chunk's compute) so the L2 latency is fully hidden.
        if (c0 + CH < cbase + KSPLIT) {
            const float4* nb = emb4 + ((size_t)(c0 + CH) << 4);
            #pragma unroll
            for (int j = 0; j < 4; j++)
                pf[j] = nb[(size_t)(tid + j * TPB)];
        }

        u64 acc[4][4];   // [code][vector-pair]
        #pragma unroll
        for (int cc = 0; cc < 4; cc++)
            #pragma unroll
            for (int vp = 0; vp < 4; vp++) acc[cc][vp] = 0ull;

        #pragma unroll 4
        for (int d2 = 0; d2 < 32; d2++) {     // 2 d's per iteration
            u64 xf[2][4];
            #pragma unroll
            for (int dd = 0; dd < 2; dd++) {
                unsigned a = xs + (d2 * 2 + dd) * 512 + xlane;
                LDS_V2U64(xf[dd][0], xf[dd][1], a);
                LDS_V2U64(xf[dd][2], xf[dd][3], a ^ 16);
            }
            #pragma unroll
            for (int cc = 0; cc < 4; cc++) {
                float e0, e1;
                LDS_V2F32(e0, e1, esb + (tc * 4 + cc) * 256 + d2 * 8);
                u64 ed0, ed1;
                PACK_X2(ed0, e0, e0);
                PACK_X2(ed1, e1, e1);
                #pragma unroll
                for (int vp = 0; vp < 4; vp++) {
                    FMA_X2(acc[cc][vp], ed0, xf[0][vp], acc[cc][vp]);
                    FMA_X2(acc[cc][vp], ed1, xf[1][vp], acc[cc][vp]);
                }
            }
        }

        // Scores + running argmin (codes ascending; strict < keeps first min)
        #pragma unroll
        for (int cc = 0; cc < 4; cc++) {
            int c = c0 + tc * 4 + cc;
            float enc = __ldg(&g_enorm[c]);
            #pragma unroll
            for (int vp = 0; vp < 4; vp++) {
                float d0, d1;
                UNPACK_X2(d0, d1, acc[cc][vp]);
                float s0 = fmaf(-2.0f, d0, enc);
                float s1 = fmaf(-2.0f, d1, enc);
                if (s0 < best[2 * vp])     { best[2 * vp]     = s0; bidx[2 * vp]     = c; }
                if (s1 < best[2 * vp + 1]) { best[2 * vp + 1] = s1; bidx[2 * vp + 1] = c; }
            }
        }
    }

    // e tile is dead now; reuse its first KB for the argmin cells.
    __syncthreads();
    if (tid < VV) red2[tid] = 0xFFFFFFFFFFFFFFFFull;
    __syncthreads();

    // In-CTA argmin: lexicographic (score, idx) via packed u64 atomicMin.
    // ordered-uint encoding of fp32 preserves <; low bits carry code index so
    // exact ties resolve to the smallest index (jnp.argmin semantics).
    #pragma unroll
    for (int k = 0; k < 8; k++) {
        unsigned fb = __float_as_uint(best[k]);
        fb = (fb & 0x80000000u) ? ~fb : (fb | 0x80000000u);
        u64 key = ((u64)fb << 32) | (unsigned)bidx[k];
        atomicMin(&red2[tv * 8 + k], key);
    }
    __syncthreads();

    // Cross-CTA merge: one global atomicMin per vector.
    if (tid < VV)
        atomicMin(&g_keys[(size_t)pair * VV + tid], red2[tid]);

    // Pair handshake: the SECOND CTA to arrive sees both halves' keys
    // (its fence-before-ticket + the peer's fence-before-ticket) and runs
    // the epilogue from its own smem x tile.
    __threadfence();
    __syncthreads();
    if (tid == 0) {
        unsigned second = (atomicAdd(&g_pair[pair], 1u) == 1u) ? 1u : 0u;
        STS_U32(sbase + FLAG_OFF, second);
    }
    __syncthreads();
    unsigned do_epi;
    LDS_U32(do_epi, sbase + FLAG_OFF);
    if (!do_epi) return;   // first arriver frees its SM slot

    // Epilogue: thread v < 128 owns vector v. Keys are final.
    if (tid < VV) {
        const int v = tid;
        const u64 key = *((const volatile u64*)&g_keys[(size_t)pair * VV + v]);
        const int c = (int)(key & 1023u);
        atomicAdd(&g_counts[c], 1);

        const float4* er4 = (const float4*)(emb + (size_t)c * D_DIM);
        float* op  = outq + ((size_t)(b << 6)) * T_LEN + t0 + v;
        float* dwp = g_dw + (size_t)c * D_DIM;

        const int p = v >> 1;
        const unsigned fbyte = ((((unsigned)(p & ~1)) << 3) ^ ((((unsigned)p >> 4) & 3) << 4))
                             + (((unsigned)(p & 1)) << 3) + (((unsigned)(v & 1)) << 2);
        #pragma unroll
        for (int i = 0; i < D_DIM / 4; i++) {
            float4 ev = er4[i];
            op[(size_t)(4 * i + 0) * T_LEN] = ev.x;
            op[(size_t)(4 * i + 1) * T_LEN] = ev.y;
            op[(size_t)(4 * i + 2) * T_LEN] = ev.z;
            op[(size_t)(4 * i + 3) * T_LEN] = ev.w;
            float x0, x1, x2, x3;
            LDS_F32(x0, xs + (4 * i + 0) * 512 + fbyte);
            LDS_F32(x1, xs + (4 * i + 1) * 512 + fbyte);
            LDS_F32(x2, xs + (4 * i + 2) * 512 + fbyte);
            LDS_F32(x3, xs + (4 * i + 3) * 512 + fbyte);
            REDG_ADD_V4F32(dwp + 4 * i, x0, x1, x2, x3);
        }
    }

    // Global finalize: last of the 1024 epilogue CTAs computes new_embeddings.
    __threadfence();
    __syncthreads();
    if (tid == 0) {
        unsigned last = (atomicAdd(&g_done, 1u) == (unsigned)NPAIR - 1u) ? 1u : 0u;
        STS_U32(sbase + FLAG_OFF, last);
    }
    __syncthreads();
    unsigned is_last;
    LDS_U32(is_last, sbase + FLAG_OFF);
    if (is_last) {
        const float nf = (float)N_VEC;
        const float denom = nf + (float)K_CODES * 1e-5f;
        #pragma unroll 4
        for (int i4 = tid; i4 < K_CODES * D_DIM / 4; i4 += TPB) {
            int c = i4 >> 4;
            float cnt = (float)g_counts[c];
            float inv = denom / ((cnt + 1e-5f) * nf);   // 1/cluster_size
            const float4 dv = *(const float4*)(g_dw + i4 * 4);
            float4 ov;
            ov.x = dv.x * inv; ov.y = dv.y * inv;
            ov.z = dv.z * inv; ov.w = dv.w * inv;
            *(float4*)(out_emb + i4 * 4) = ov;
        }
    }
}

extern "C" void kernel_launch(void* const* d_in, const int* in_sizes, int n_in,
                              void* d_out, int out_size) {
    const float* x   = (const float*)d_in[0];
    const float* emb = (const float*)d_in[1];
    float* out     = (float*)d_out;
    float* outq    = out;                                  // [B, D, T]
    float* out_emb = out + (size_t)N_VEC * D_DIM;          // [K, D]

    init_kernel<<<N_VEC / 256, 256>>>(emb);
    assign_kernel<<<NCTA, TPB, SMEM_BYTES>>>(x, emb, outq, out_emb);
}

// round 16
// speedup vs baseline: 1.1379x; 1.1379x over previous
#include <cuda_runtime.h>

// Problem constants
#define K_CODES 1024
#define D_DIM   64
#define B_SZ    16
#define T_LEN   8192
#define N_VEC   (B_SZ * T_LEN)     // 131072 vectors
#define TPB     128                // 4 CTAs/SM -> 16 warps in 4 indep groups
#define VV      128                // vectors per CTA
#define CH      32                 // codes per e buffer (double-buffered)
#define NCHUNK  (K_CODES / CH)     // 32
#define NCTA    (N_VEC / VV)       // 1024 assign CTAs

typedef unsigned long long u64;

// Packed fp32x2 ops (sm_103a; PTX-only, ptxas never auto-fuses)
#define FMA_X2(d, a, b, c) \
    asm("fma.rn.f32x2 %0, %1, %2, %3;" : "=l"(d) : "l"(a), "l"(b), "l"(c))
#define PACK_X2(d, lo, hi) \
    asm("mov.b64 %0, {%1, %2};" : "=l"(d) : "f"(lo), "f"(hi))
#define UNPACK_X2(lo, hi, s) \
    asm("mov.b64 {%0, %1}, %2;" : "=f"(lo), "=f"(hi) : "l"(s))
#define LDS_V2U64(p0, p1, addr) \
    asm("ld.shared.v2.u64 {%0, %1}, [%2];" : "=l"(p0), "=l"(p1) : "r"(addr))
#define LDS_V2F32(f0, f1, addr) \
    asm("ld.shared.v2.f32 {%0, %1}, [%2];" : "=f"(f0), "=f"(f1) : "r"(addr))
#define STS_V4F32(addr, f0, f1, f2, f3) \
    asm volatile("st.shared.v4.f32 [%0], {%1,%2,%3,%4};" \
        :: "r"(addr), "f"(f0), "f"(f1), "f"(f2), "f"(f3))
#define LDS_F32(f, addr) \
    asm("ld.shared.f32 %0, [%1];" : "=f"(f) : "r"(addr))
#define STS_U32(addr, v) \
    asm volatile("st.shared.u32 [%0], %1;" :: "r"(addr), "r"(v) : "memory")
#define LDS_U32(v, addr) \
    asm("ld.shared.u32 %0, [%1];" : "=r"(v) : "r"(addr))
// cp.async 16B (sm_80+ baseline)
#define CP_ASYNC16(smem_addr, gptr) \
    asm volatile("cp.async.cg.shared.global [%0], [%1], 16;" \
        :: "r"(smem_addr), "l"(gptr) : "memory")
#define CP_ASYNC_COMMIT() asm volatile("cp.async.commit_group;" ::: "memory")
#define CP_ASYNC_WAIT0()  asm volatile("cp.async.wait_group 0;" ::: "memory")
// Vector float reduction (sm_90+ baseline)
#define REDG_ADD_V4F32(ptr, a0, a1, a2, a3) \
    asm volatile("red.global.add.v4.f32 [%0], {%1,%2,%3,%4};" \
        :: "l"(ptr), "f"(a0), "f"(a1), "f"(a2), "f"(a3) : "memory")

// Scratch (allocation-free rule -> __device__ globals)
__device__ float    g_dw[K_CODES * D_DIM];
__device__ int      g_counts[K_CODES];
__device__ float    g_enorm[K_CODES];
__device__ unsigned g_done;     // last-CTA ticket; reset by init each call

// Dynamic smem layout (bytes) — exactly 48KB, zero static smem:
//   [0, 32768)       x tile: 64 d-rows x 512B (swizzled f32x2 vector-pairs)
//   [32768, 40960)   e buffer 0: 32 code-rows x 256B (linear)
//   [40960, 49152)   e buffer 1
//   red2 (128 u64 argmin cells) ALIASES start of e buffer 0 (dead after
//   the last chunk's compute, which reads buffer 1; barrier-separated).
//   flag word at ES_OFF + 2048 (also dead space at that point).
#define XS_OFF   0
#define ES_OFF   32768
#define EBUF_BYTES 8192
#define FLAG_OFF (ES_OFF + 2048)
#define SMEM_BYTES 49152

// Init: zero dw/counts/ticket + code norms (warp per code, shuffle reduce).
// 32768 threads = 1024 warps, one warp per code.
__global__ void init_kernel(const float* __restrict__ emb) {
    const int gt   = blockIdx.x * blockDim.x + threadIdx.x;
    const int lane = gt & 31;
    const int code = gt >> 5;

    g_dw[gt] = 0.0f;
    g_dw[gt + 32768] = 0.0f;
    if (gt < K_CODES) g_counts[gt] = 0;
    if (gt == 0) g_done = 0;

    const float* e = emb + code * D_DIM;
    float v0 = e[lane], v1 = e[lane + 32];
    float s = fmaf(v0, v0, v1 * v1);
    #pragma unroll
    for (int o = 16; o > 0; o >>= 1)
        s += __shfl_xor_sync(0xFFFFFFFFu, s, o);
    if (lane == 0) g_enorm[code] = s;
}

// GEMM-tiled assignment (+ fused finalize via last-CTA ticket).
// CTA: 128 vectors x 1024 codes in 32 chunks of 32 (cp.async double-buffered
// e). Thread (tv = tid&15, tc = tid>>4 in 0..7): micro-tile 8 vectors x
// 4 codes per chunk. Dot via fma.rn.f32x2 packed over vector pairs.
// TPB=128 with 4 CTAs/SM: 4 independent barrier groups decorrelate LDS
// bursts; one barrier per chunk.
__global__ void __launch_bounds__(TPB, 4) assign_kernel(
    const float* __restrict__ x,
    const float* __restrict__ emb,
    float* __restrict__ outq,
    float* __restrict__ out_emb)
{
    extern __shared__ char sm[];
    const unsigned sbase = (unsigned)__cvta_generic_to_shared(sm);
    const unsigned xs  = sbase + XS_OFF;
    const unsigned esb = sbase + ES_OFF;
    u64* red2 = (u64*)(sm + ES_OFF);   // aliases e buf0 (dead at that point)

    const int tid = threadIdx.x;
    const int tv  = tid & 15;
    const int tc  = tid >> 4;                 // 0..7
    const int blk = blockIdx.x;
    const int b   = blk >> 6;                 // 64 CTAs per batch row
    const int t0  = (blk << 7) & (T_LEN - 1); // 128 vectors per CTA

    // Kick off chunk 0's e-load immediately (overlaps x-tile prologue).
    // 8KB / 128 threads = 4 x 16B per thread; e rows are linear [code][d].
    {
        const float* src = emb;   // chunk 0 = codes 0..31
        #pragma unroll
        for (int j = 0; j < 4; j++) {
            int i4 = tid + j * TPB;                       // 0..511
            CP_ASYNC16(esb + i4 * 16, src + i4 * 4);
        }
        CP_ASYNC_COMMIT();
    }

    // Load x tile: xs[d][swizzled pair columns].
    // Pair p lives at byte (((p&~1)<<3) ^ (((p>>4)&3)<<4)) + ((p&1)<<3).
    {
        const float* xb = x + ((size_t)(b << 6)) * T_LEN + t0;
        #pragma unroll
        for (int i4 = tid; i4 < (D_DIM * VV) / 4; i4 += TPB) {   // 2048 float4
            int d = i4 >> 5, v4 = i4 & 31;
            float4 val = *(const float4*)(xb + (size_t)d * T_LEN + v4 * 4);
            unsigned a = xs + d * 512 + (((unsigned)(v4 << 4)) ^ (((v4 >> 3) & 3) << 4));
            STS_V4F32(a, val.x, val.y, val.z, val.w);
        }
    }

    float best[8];
    int   bidx[8];
    #pragma unroll
    for (int k = 0; k < 8; k++) { best[k] = 3.402823466e38f; bidx[k] = 0; }

    // Per-thread swizzled x-line base: first 16B at xlane, second at xlane^16.
    const unsigned xlane = ((unsigned)(tv * 32)) ^ ((((unsigned)tv >> 2) & 3) << 4);

    for (int cc0 = 0; cc0 < NCHUNK; cc0++) {
        const unsigned eb = esb + (cc0 & 1) * EBUF_BYTES;
        CP_ASYNC_WAIT0();     // my async group for chunk cc0 done
        __syncthreads();      // all threads' chunk data in + prev buf free

        // Prefetch chunk cc0+1 into the other buffer (it was last read in
        // chunk cc0-1; the barrier above guarantees everyone is done).
        if (cc0 + 1 < NCHUNK) {
            const float* src = emb + (size_t)(cc0 + 1) * CH * D_DIM;
            const unsigned nb = esb + ((cc0 + 1) & 1) * EBUF_BYTES;
            #pragma unroll
            for (int j = 0; j < 4; j++) {
                int i4 = tid + j * TPB;
                CP_ASYNC16(nb + i4 * 16, src + i4 * 4);
            }
            CP_ASYNC_COMMIT();
        }

        u64 acc[4][4];   // [code][vector-pair]
        #pragma unroll
        for (int cc = 0; cc < 4; cc++)
            #pragma unroll
            for (int vp = 0; vp < 4; vp++) acc[cc][vp] = 0ull;

        #pragma unroll 4
        for (int d2 = 0; d2 < 32; d2++) {     // 2 d's per iteration
            u64 xf[2][4];
            #pragma unroll
            for (int dd = 0; dd < 2; dd++) {
                unsigned a = xs + (d2 * 2 + dd) * 512 + xlane;
                LDS_V2U64(xf[dd][0], xf[dd][1], a);
                LDS_V2U64(xf[dd][2], xf[dd][3], a ^ 16);
            }
            #pragma unroll
            for (int cc = 0; cc < 4; cc++) {
                float e0, e1;
                LDS_V2F32(e0, e1, eb + (tc * 4 + cc) * 256 + d2 * 8);
                u64 ed0, ed1;
                PACK_X2(ed0, e0, e0);
                PACK_X2(ed1, e1, e1);
                #pragma unroll
                for (int vp = 0; vp < 4; vp++) {
                    FMA_X2(acc[cc][vp], ed0, xf[0][vp], acc[cc][vp]);
                    FMA_X2(acc[cc][vp], ed1, xf[1][vp], acc[cc][vp]);
                }
            }
        }

        // Scores + running argmin (codes ascending; strict < keeps first min)
        #pragma unroll
        for (int cc = 0; cc < 4; cc++) {
            int c = cc0 * CH + tc * 4 + cc;
            float enc = __ldg(&g_enorm[c]);
            #pragma unroll
            for (int vp = 0; vp < 4; vp++) {
                float d0, d1;
                UNPACK_X2(d0, d1, acc[cc][vp]);
                float s0 = fmaf(-2.0f, d0, enc);
                float s1 = fmaf(-2.0f, d1, enc);
                if (s0 < best[2 * vp])     { best[2 * vp]     = s0; bidx[2 * vp]     = c; }
                if (s1 < best[2 * vp + 1]) { best[2 * vp + 1] = s1; bidx[2 * vp + 1] = c; }
            }
        }
    }

    // Buffer 0 is dead now (last chunk read buffer 1); reuse for argmin cells.
    __syncthreads();
    red2[tid] = 0xFFFFFFFFFFFFFFFFull;
    __syncthreads();

    // Cross-thread argmin: lexicographic (score, idx) via packed u64 atomicMin.
    // ordered-uint encoding of fp32 preserves <; low bits carry code index so
    // exact ties resolve to the smallest index (jnp.argmin semantics).
    #pragma unroll
    for (int k = 0; k < 8; k++) {
        unsigned fb = __float_as_uint(best[k]);
        fb = (fb & 0x80000000u) ? ~fb : (fb | 0x80000000u);
        u64 key = ((u64)fb << 32) | (unsigned)bidx[k];
        atomicMin(&red2[tv * 8 + k], key);
    }
    __syncthreads();

    // Epilogue: thread v owns vector v (TPB == VV).
    {
        const int v = tid;
        const int c = (int)(red2[v] & 1023u);
        atomicAdd(&g_counts[c], 1);

        const float4* er4 = (const float4*)(emb + (size_t)c * D_DIM);
        float* op  = outq + ((size_t)(b << 6)) * T_LEN + t0 + v;
        float* dwp = g_dw + (size_t)c * D_DIM;

        const int p = v >> 1;
        const unsigned fbyte = ((((unsigned)(p & ~1)) << 3) ^ ((((unsigned)p >> 4) & 3) << 4))
                             + (((unsigned)(p & 1)) << 3) + (((unsigned)(v & 1)) << 2);
        #pragma unroll
        for (int i = 0; i < D_DIM / 4; i++) {
            float4 ev = er4[i];
            op[(size_t)(4 * i + 0) * T_LEN] = ev.x;
            op[(size_t)(4 * i + 1) * T_LEN] = ev.y;
            op[(size_t)(4 * i + 2) * T_LEN] = ev.z;
            op[(size_t)(4 * i + 3) * T_LEN] = ev.w;
            float x0, x1, x2, x3;
            LDS_F32(x0, xs + (4 * i + 0) * 512 + fbyte);
            LDS_F32(x1, xs + (4 * i + 1) * 512 + fbyte);
            LDS_F32(x2, xs + (4 * i + 2) * 512 + fbyte);
            LDS_F32(x3, xs + (4 * i + 3) * 512 + fbyte);
            REDG_ADD_V4F32(dwp + 4 * i, x0, x1, x2, x3);
        }
    }

    // ---- Fused finalize: last CTA to arrive computes new_embeddings. ----
    // Fence makes this CTA's dw/counts writes visible; the ticket atomic
    // orders them; the winner sees all 1024 CTAs' contributions.
    __threadfence();
    __syncthreads();
    if (tid == 0) {
        unsigned last = (atomicAdd(&g_done, 1u) == NCTA - 1u) ? 1u : 0u;
        STS_U32(sbase + FLAG_OFF, last);
    }
    __syncthreads();
    unsigned is_last;
    LDS_U32(is_last, sbase + FLAG_OFF);
    if (is_last) {
        const float nf = (float)N_VEC;
        const float denom = nf + (float)K_CODES * 1e-5f;
        #pragma unroll 4
        for (int i4 = tid; i4 < K_CODES * D_DIM / 4; i4 += TPB) {
            int c = i4 >> 4;
            float cnt = (float)g_counts[c];
            float inv = denom / ((cnt + 1e-5f) * nf);   // 1/cluster_size
            const float4 dv = *(const float4*)(g_dw + i4 * 4);
            float4 ov;
            ov.x = dv.x * inv; ov.y = dv.y * inv;
            ov.z = dv.z * inv; ov.w = dv.w * inv;
            *(float4*)(out_emb + i4 * 4) = ov;
        }
    }
}

extern "C" void kernel_launch(void* const* d_in, const int* in_sizes, int n_in,
                              void* d_out, int out_size) {
    const float* x   = (const float*)d_in[0];
    const float* emb = (const float*)d_in[1];
    float* out     = (float*)d_out;
    float* outq    = out;                                  // [B, D, T]
    float* out_emb = out + (size_t)N_VEC * D_DIM;          // [K, D]

    init_kernel<<<128, 256>>>(emb);
    assign_kernel<<<NCTA, TPB, SMEM_BYTES>>>(x, emb, outq, out_emb);
}